// round 1
// baseline (speedup 1.0000x reference)
#include <cuda_runtime.h>
#include <math.h>

#define B_ 4
#define D_ 512
#define S_ 2048
#define L_ 8921

// Scratch for K and V, [B, S, D] row-major (d contiguous)
__device__ float g_K[B_ * S_ * D_];
__device__ float g_V[B_ * S_ * D_];

#define BM 64
#define BN 64
#define BK 16

__device__ __forceinline__ float elu_f(float x) { return x > 0.f ? x : expm1f(x); }

// ---------------------------------------------------------------------------
// Kernel 1: K/V projection.  out[b,s,o] = elu( sum_d W[o,d] * H[b,d,s] + bias[o] )
// grid: (D/BN, B*S/BM, 2)   z=0 -> K (Wk,bk), z=1 -> V (Wv,bv)
// ---------------------------------------------------------------------------
__global__ __launch_bounds__(256) void kv_kernel(
    const float* __restrict__ H,
    const float* __restrict__ Wk, const float* __restrict__ bk,
    const float* __restrict__ Wv, const float* __restrict__ bv)
{
    const float* W    = blockIdx.z ? Wv : Wk;
    const float* bias = blockIdx.z ? bv : bk;
    float* out        = blockIdx.z ? g_V : g_K;

    __shared__ float As[BK][BM];   // As[d][m]
    __shared__ float Bs[BK][BN];   // Bs[d][o]

    const int m0 = blockIdx.y * BM;          // m = b*S + s  (S % BM == 0, no b straddle)
    const int n0 = blockIdx.x * BN;          // o
    const int b  = m0 / S_;
    const int s0 = m0 % S_;

    const int t  = threadIdx.x;
    const int tx = t & 15, ty = t >> 4;

    float acc[4][4] = {};

    const float* Hb = H + (size_t)b * D_ * S_;

    for (int k0 = 0; k0 < D_; k0 += BK) {
        // A tile: H[b, k0+dl, s0+ml], m contiguous -> vectorized
        {
            int e  = t * 4;
            int ml = e & 63, dl = e >> 6;
            float4 v = *(const float4*)(Hb + (size_t)(k0 + dl) * S_ + s0 + ml);
            *(float4*)&As[dl][ml] = v;
        }
        // B tile: W[(n0+ol)*D + k0+dl], d contiguous -> vectorized, transpose into smem
        {
            int e  = t * 4;
            int ol = e >> 4, dl = e & 15;
            float4 v = *(const float4*)(W + (size_t)(n0 + ol) * D_ + k0 + dl);
            Bs[dl + 0][ol] = v.x; Bs[dl + 1][ol] = v.y;
            Bs[dl + 2][ol] = v.z; Bs[dl + 3][ol] = v.w;
        }
        __syncthreads();
#pragma unroll
        for (int k = 0; k < BK; k++) {
            float4 a4 = *(const float4*)&As[k][ty * 4];
            float4 b4 = *(const float4*)&Bs[k][tx * 4];
            float av[4] = {a4.x, a4.y, a4.z, a4.w};
            float bv2[4] = {b4.x, b4.y, b4.z, b4.w};
#pragma unroll
            for (int i = 0; i < 4; i++)
#pragma unroll
                for (int j = 0; j < 4; j++)
                    acc[i][j] += av[i] * bv2[j];
        }
        __syncthreads();
    }

#pragma unroll
    for (int i = 0; i < 4; i++) {
        int m = m0 + ty * 4 + i;   // = b*S + s
        float4 o4;
        o4.x = elu_f(acc[i][0] + bias[n0 + tx * 4 + 0]);
        o4.y = elu_f(acc[i][1] + bias[n0 + tx * 4 + 1]);
        o4.z = elu_f(acc[i][2] + bias[n0 + tx * 4 + 2]);
        o4.w = elu_f(acc[i][3] + bias[n0 + tx * 4 + 3]);
        *(float4*)(out + (size_t)m * D_ + n0 + tx * 4) = o4;
    }
}

// ---------------------------------------------------------------------------
// Kernel 2: E[b,l,s] = sum_d Q[l,d] * K[b,s,d]   (NT GEMM), written raw into A region
// grid: (S/BN, ceil(L/BM), B)
// ---------------------------------------------------------------------------
__global__ __launch_bounds__(256) void e_kernel(
    const float* __restrict__ Q, float* __restrict__ Aout)
{
    const int b  = blockIdx.z;
    const int m0 = blockIdx.y * BM;  // l
    const int n0 = blockIdx.x * BN;  // s

    __shared__ float As[BK][BM];     // As[d][l]
    __shared__ float Bs[BK][BN];     // Bs[d][s]

    const int t  = threadIdx.x;
    const int tx = t & 15, ty = t >> 4;

    float acc[4][4] = {};

    const float* Kb = g_K + (size_t)b * S_ * D_;

    for (int k0 = 0; k0 < D_; k0 += BK) {
        // Q tile: Q[(m0+ml)*D + k0+dl], d contiguous; guard l < L
        {
            int e  = t * 4;
            int ml = e >> 4, dl = e & 15;
            int l  = m0 + ml;
            float4 v = make_float4(0.f, 0.f, 0.f, 0.f);
            if (l < L_) v = *(const float4*)(Q + (size_t)l * D_ + k0 + dl);
            As[dl + 0][ml] = v.x; As[dl + 1][ml] = v.y;
            As[dl + 2][ml] = v.z; As[dl + 3][ml] = v.w;
        }
        // K tile: K[b, n0+ol, k0+dl], d contiguous
        {
            int e  = t * 4;
            int ol = e >> 4, dl = e & 15;
            float4 v = *(const float4*)(Kb + (size_t)(n0 + ol) * D_ + k0 + dl);
            Bs[dl + 0][ol] = v.x; Bs[dl + 1][ol] = v.y;
            Bs[dl + 2][ol] = v.z; Bs[dl + 3][ol] = v.w;
        }
        __syncthreads();
#pragma unroll
        for (int k = 0; k < BK; k++) {
            float4 a4 = *(const float4*)&As[k][ty * 4];
            float4 b4 = *(const float4*)&Bs[k][tx * 4];
            float av[4] = {a4.x, a4.y, a4.z, a4.w};
            float bv2[4] = {b4.x, b4.y, b4.z, b4.w};
#pragma unroll
            for (int i = 0; i < 4; i++)
#pragma unroll
                for (int j = 0; j < 4; j++)
                    acc[i][j] += av[i] * bv2[j];
        }
        __syncthreads();
    }

#pragma unroll
    for (int i = 0; i < 4; i++) {
        int l = m0 + ty * 4 + i;
        if (l < L_) {
            float4 o4 = make_float4(acc[i][0], acc[i][1], acc[i][2], acc[i][3]);
            *(float4*)(Aout + ((size_t)b * L_ + l) * S_ + n0 + tx * 4) = o4;
        }
    }
}

// ---------------------------------------------------------------------------
// Kernel 3: in-place row softmax over S=2048. grid: B*L blocks, 256 threads.
// ---------------------------------------------------------------------------
__global__ __launch_bounds__(256) void softmax_kernel(float* __restrict__ A)
{
    const size_t row = blockIdx.x;
    float* p = A + row * (size_t)S_;
    const int t = threadIdx.x;

    float v[8];
    float m = -1e30f;
#pragma unroll
    for (int i = 0; i < 8; i++) { v[i] = p[i * 256 + t]; m = fmaxf(m, v[i]); }

    __shared__ float red[256];
    red[t] = m;
    __syncthreads();
    for (int s = 128; s > 0; s >>= 1) {
        if (t < s) red[t] = fmaxf(red[t], red[t + s]);
        __syncthreads();
    }
    m = red[0];
    __syncthreads();

    float sum = 0.f;
#pragma unroll
    for (int i = 0; i < 8; i++) { v[i] = __expf(v[i] - m); sum += v[i]; }
    red[t] = sum;
    __syncthreads();
    for (int s = 128; s > 0; s >>= 1) {
        if (t < s) red[t] += red[t + s];
        __syncthreads();
    }
    float inv = 1.f / red[0];
#pragma unroll
    for (int i = 0; i < 8; i++) p[i * 256 + t] = v[i] * inv;
}

// ---------------------------------------------------------------------------
// Kernel 4: C[b,l,o] = sum_s A[b,l,s] * V[b,s,o]  (NN GEMM)
// grid: (D/BN, ceil(L/BM), B)
// ---------------------------------------------------------------------------
__global__ __launch_bounds__(256) void c_kernel(
    const float* __restrict__ A, float* __restrict__ Cout)
{
    const int b  = blockIdx.z;
    const int m0 = blockIdx.y * BM;  // l
    const int n0 = blockIdx.x * BN;  // o

    __shared__ float As[BK][BM];     // As[s][l]
    __shared__ float Bs[BK][BN];     // Bs[s][o]

    const int t  = threadIdx.x;
    const int tx = t & 15, ty = t >> 4;

    float acc[4][4] = {};

    const float* Ab = A + (size_t)b * L_ * S_;
    const float* Vb = g_V + (size_t)b * S_ * D_;

    for (int k0 = 0; k0 < S_; k0 += BK) {
        // A tile: A[l, k0+sl], s contiguous; guard l < L
        {
            int e  = t * 4;
            int ml = e >> 4, sl = e & 15;
            int l  = m0 + ml;
            float4 v = make_float4(0.f, 0.f, 0.f, 0.f);
            if (l < L_) v = *(const float4*)(Ab + (size_t)l * S_ + k0 + sl);
            As[sl + 0][ml] = v.x; As[sl + 1][ml] = v.y;
            As[sl + 2][ml] = v.z; As[sl + 3][ml] = v.w;
        }
        // V tile: V[b, k0+sl, n0+ol], o contiguous -> direct vectorized
        {
            int e  = t * 4;
            int ol = e & 63, sl = e >> 6;
            float4 v = *(const float4*)(Vb + (size_t)(k0 + sl) * D_ + n0 + ol);
            *(float4*)&Bs[sl][ol] = v;
        }
        __syncthreads();
#pragma unroll
        for (int k = 0; k < BK; k++) {
            float4 a4 = *(const float4*)&As[k][ty * 4];
            float4 b4 = *(const float4*)&Bs[k][tx * 4];
            float av[4] = {a4.x, a4.y, a4.z, a4.w};
            float bv2[4] = {b4.x, b4.y, b4.z, b4.w};
#pragma unroll
            for (int i = 0; i < 4; i++)
#pragma unroll
                for (int j = 0; j < 4; j++)
                    acc[i][j] += av[i] * bv2[j];
        }
        __syncthreads();
    }

#pragma unroll
    for (int i = 0; i < 4; i++) {
        int l = m0 + ty * 4 + i;
        if (l < L_) {
            float4 o4 = make_float4(acc[i][0], acc[i][1], acc[i][2], acc[i][3]);
            *(float4*)(Cout + ((size_t)b * L_ + l) * D_ + n0 + tx * 4) = o4;
        }
    }
}

// ---------------------------------------------------------------------------
extern "C" void kernel_launch(void* const* d_in, const int* in_sizes, int n_in,
                              void* d_out, int out_size)
{
    const float* H  = (const float*)d_in[0];
    const float* Wk = (const float*)d_in[1];
    const float* bk = (const float*)d_in[2];
    const float* Wv = (const float*)d_in[3];
    const float* bv = (const float*)d_in[4];
    const float* Q  = (const float*)d_in[5];

    float* out  = (float*)d_out;
    float* Cout = out;                                  // [B, L, D]
    float* Aout = out + (size_t)B_ * L_ * D_;           // [B, L, S]

    dim3 blk(256);

    kv_kernel<<<dim3(D_ / BN, (B_ * S_) / BM, 2), blk>>>(H, Wk, bk, Wv, bv);
    e_kernel<<<dim3(S_ / BN, (L_ + BM - 1) / BM, B_), blk>>>(Q, Aout);
    softmax_kernel<<<dim3(B_ * L_), blk>>>(Aout);
    c_kernel<<<dim3(D_ / BN, (L_ + BM - 1) / BM, B_), blk>>>(Aout, Cout);
}

// round 4
// speedup vs baseline: 2.5191x; 2.5191x over previous
#include <cuda_runtime.h>
#include <cuda_bf16.h>
#include <math.h>
#include <cstdint>

#define B_ 4
#define D_ 512
#define S_ 2048
#define L_ 8921

// bf16x2 split operands
__device__ __nv_bfloat16 g_Kh[B_ * S_ * D_];
__device__ __nv_bfloat16 g_Kl[B_ * S_ * D_];
__device__ __nv_bfloat16 g_VTh[B_ * D_ * S_];
__device__ __nv_bfloat16 g_VTl[B_ * D_ * S_];
__device__ __nv_bfloat16 g_Qh[L_ * D_];
__device__ __nv_bfloat16 g_Ql[L_ * D_];
__device__ __nv_bfloat16 g_Ah[(size_t)B_ * L_ * S_];
__device__ __nv_bfloat16 g_Al[(size_t)B_ * L_ * S_];

// ---------------------------------------------------------------------------
// helpers
// ---------------------------------------------------------------------------
__device__ __forceinline__ uint32_t smem_to_u32(const void* p) {
    uint32_t a;
    asm("{ .reg .u64 t; cvta.to.shared.u64 t, %1; cvt.u32.u64 %0, t; }" : "=r"(a) : "l"(p));
    return a;
}
__device__ __forceinline__ void cp_async16(uint32_t dst, const void* src) {
    asm volatile("cp.async.cg.shared.global [%0], [%1], 16;" :: "r"(dst), "l"(src));
}
#define CP_COMMIT() asm volatile("cp.async.commit_group;" ::: "memory")
#define CP_WAIT(n)  asm volatile("cp.async.wait_group %0;" :: "n"(n) : "memory")

__device__ __forceinline__ void mma_bf16(float* d, const uint32_t* a, const uint32_t* b) {
    asm volatile(
        "mma.sync.aligned.m16n8k16.row.col.f32.bf16.bf16.f32 "
        "{%0,%1,%2,%3}, {%4,%5,%6,%7}, {%8,%9}, {%0,%1,%2,%3};"
        : "+f"(d[0]), "+f"(d[1]), "+f"(d[2]), "+f"(d[3])
        : "r"(a[0]), "r"(a[1]), "r"(a[2]), "r"(a[3]), "r"(b[0]), "r"(b[1]));
}
__device__ __forceinline__ void ldmx4(uint32_t* r, uint32_t addr) {
    asm volatile("ldmatrix.sync.aligned.m8n8.x4.shared.b16 {%0,%1,%2,%3}, [%4];"
        : "=r"(r[0]), "=r"(r[1]), "=r"(r[2]), "=r"(r[3]) : "r"(addr));
}
__device__ __forceinline__ void ldmx2(uint32_t* r, uint32_t addr) {
    asm volatile("ldmatrix.sync.aligned.m8n8.x2.shared.b16 {%0,%1}, [%2];"
        : "=r"(r[0]), "=r"(r[1]) : "r"(addr));
}

__device__ __forceinline__ float elu_f(float x) { return x > 0.f ? x : expm1f(x); }

__device__ __forceinline__ void split_bf16(float x, __nv_bfloat16& hi, __nv_bfloat16& lo) {
    hi = __float2bfloat16(x);
    lo = __float2bfloat16(x - __bfloat162float(hi));
}

// ===========================================================================
// bf16x2 mma.sync GEMM:  C[m,n] = sum_k A[m,k]*B[n,k]  (operands split hi/lo)
// Block 128x128, TK=32 (bf16 elems), 8 warps (warp tile 64x32), 4-stage pipe.
// smem rows padded to 80B (64B data) -> ldmatrix conflict-free.
// ===========================================================================
#define TM 128
#define TN 128
#define TK 32
#define ROWB 80                          // 32 bf16 = 64B + 16B pad
#define SUB  (128 * ROWB)                // 10240 per sub-tile
#define STAGE (4 * SUB)                  // Ah | Al | Bh | Bl = 40960
#define NSTG 4
#define GEMM_SMEM (NSTG * STAGE)         // 163840

__global__ __launch_bounds__(256) void gemm_mma(
    const __nv_bfloat16* __restrict__ Ah, const __nv_bfloat16* __restrict__ Al,
    int lda, size_t sA,
    const __nv_bfloat16* __restrict__ Bh, const __nv_bfloat16* __restrict__ Bl,
    int ldb, size_t sB,
    float* __restrict__ C, int ldc, size_t sC,
    int kblocks, int Mtotal)
{
    extern __shared__ char smem[];
    const uint32_t sm0 = smem_to_u32(smem);

    const int t    = threadIdx.x;
    const int wid  = t >> 5, lane = t & 31;
    const int gid  = lane >> 2, tig = lane & 3;
    const int b    = blockIdx.z;
    const int m0   = blockIdx.y * TM;
    const int n0   = blockIdx.x * TN;

    Ah += (size_t)b * sA;  Al += (size_t)b * sA;
    Bh += (size_t)b * sB;  Bl += (size_t)b * sB;
    C  += (size_t)b * sC;

    const int wm0 = (wid & 1) * 64;
    const int wn0 = (wid >> 1) * 32;

    float acc[4][4][4];
#pragma unroll
    for (int i = 0; i < 4; i++)
#pragma unroll
        for (int j = 0; j < 4; j++)
#pragma unroll
            for (int q = 0; q < 4; q++) acc[i][j][q] = 0.f;

    // ---- stage loader: 2048 x 16B chunks (4 sub-tiles x 128 rows x 4 chunks)
    auto issue_stage = [&](int kb, int stg) {
        const uint32_t sbase = sm0 + stg * STAGE;
        const int k0 = kb * TK;
#pragma unroll
        for (int it = 0; it < 8; it++) {
            int idx = t + it * 256;
            int sub = idx >> 9;            // 0:Ah 1:Al 2:Bh 3:Bl
            int r   = (idx >> 2) & 127;
            int c   = idx & 3;
            uint32_t dst = sbase + sub * SUB + r * ROWB + c * 16;
            const __nv_bfloat16* src;
            if (sub < 2) {
                int gr = m0 + r; if (gr >= Mtotal) gr = Mtotal - 1;
                src = (sub == 0 ? Ah : Al) + (size_t)gr * lda + k0 + c * 8;
            } else {
                src = (sub == 2 ? Bh : Bl) + (size_t)(n0 + r) * ldb + k0 + c * 8;
            }
            cp_async16(dst, src);
        }
    };

    // ldmatrix lane addressing offsets
    const int arow = lane & 15;            // A: rows 0..15 of frag
    const int aoff = (lane >> 4) * 16;     // +16B for k 8..15
    const int brow = lane & 7;             // B: rows 0..7
    const int boff = ((lane >> 3) & 1) * 16;

    for (int p = 0; p < NSTG - 1 && p < kblocks; p++) { issue_stage(p, p); CP_COMMIT(); }

    for (int kb = 0; kb < kblocks; kb++) {
        CP_WAIT(NSTG - 2);
        __syncthreads();
        {
            int nk = kb + NSTG - 1;
            if (nk < kblocks) issue_stage(nk, nk % NSTG);
            CP_COMMIT();
        }

        const uint32_t sbase = sm0 + (kb % NSTG) * STAGE;

#pragma unroll
        for (int ks = 0; ks < 2; ks++) {               // 2 x k16 per TK=32
            uint32_t ah[4][4], al[4][4], bh[4][2], bl[4][2];
#pragma unroll
            for (int mt = 0; mt < 4; mt++) {
                uint32_t ra = (wm0 + mt * 16 + arow) * ROWB + ks * 32 + aoff;
                ldmx4(ah[mt], sbase + 0 * SUB + ra);
                ldmx4(al[mt], sbase + 1 * SUB + ra);
            }
#pragma unroll
            for (int nt = 0; nt < 4; nt++) {
                uint32_t rb = (wn0 + nt * 8 + brow) * ROWB + ks * 32 + boff;
                ldmx2(bh[nt], sbase + 2 * SUB + rb);
                ldmx2(bl[nt], sbase + 3 * SUB + rb);
            }
#pragma unroll
            for (int mt = 0; mt < 4; mt++)
#pragma unroll
                for (int nt = 0; nt < 4; nt++) {
                    mma_bf16(acc[mt][nt], ah[mt], bh[nt]);
                    mma_bf16(acc[mt][nt], ah[mt], bl[nt]);
                    mma_bf16(acc[mt][nt], al[mt], bh[nt]);
                }
        }
    }

    // ---- epilogue ----
#pragma unroll
    for (int mt = 0; mt < 4; mt++) {
        int r0 = m0 + wm0 + mt * 16 + gid;
#pragma unroll
        for (int nt = 0; nt < 4; nt++) {
            int c0 = n0 + wn0 + nt * 8 + 2 * tig;
            if (r0 < Mtotal)
                *(float2*)(C + (size_t)r0 * ldc + c0) =
                    make_float2(acc[mt][nt][0], acc[mt][nt][1]);
            if (r0 + 8 < Mtotal)
                *(float2*)(C + (size_t)(r0 + 8) * ldc + c0) =
                    make_float2(acc[mt][nt][2], acc[mt][nt][3]);
        }
    }
}

// ===========================================================================
// Q split:  g_Qh/g_Ql = bf16x2(Q).   L*D = 8921*512 = 8921 blocks x 512 elems
// ===========================================================================
__global__ __launch_bounds__(256) void split_q(const float* __restrict__ Q)
{
    int i = blockIdx.x * 512 + threadIdx.x * 2;
    float2 v = *(const float2*)(Q + i);
    __nv_bfloat16 h0, l0, h1, l1;
    split_bf16(v.x, h0, l0);
    split_bf16(v.y, h1, l1);
    *(__nv_bfloat162*)(g_Qh + i) = __nv_bfloat162(h0, h1);
    *(__nv_bfloat162*)(g_Ql + i) = __nv_bfloat162(l0, l1);
}

// ===========================================================================
// KV projection (fp32 SIMT), epilogue splits to bf16x2.
// K -> [B,S,D], V -> transposed [B,D,S]
// ===========================================================================
#define BM 64
#define BN 64
#define BKk 16

__global__ __launch_bounds__(256) void kv_kernel(
    const float* __restrict__ H,
    const float* __restrict__ Wk, const float* __restrict__ bk,
    const float* __restrict__ Wv, const float* __restrict__ bv)
{
    const float* W    = blockIdx.z ? Wv : Wk;
    const float* bias = blockIdx.z ? bv : bk;
    const bool   isV  = blockIdx.z;

    __shared__ float As[BKk][BM];
    __shared__ float Bs[BKk][BN];

    const int m0 = blockIdx.y * BM;   // b*S + s
    const int n0 = blockIdx.x * BN;   // o
    const int b  = m0 / S_;
    const int s0 = m0 % S_;

    const int t  = threadIdx.x;
    const int tx = t & 15, ty = t >> 4;

    float acc[4][4] = {};
    const float* Hb = H + (size_t)b * D_ * S_;

    for (int k0 = 0; k0 < D_; k0 += BKk) {
        {
            int e = t * 4;
            int ml = e & 63, dl = e >> 6;
            float4 v = *(const float4*)(Hb + (size_t)(k0 + dl) * S_ + s0 + ml);
            *(float4*)&As[dl][ml] = v;
        }
        {
            int e = t * 4;
            int ol = e >> 4, dl = e & 15;
            float4 v = *(const float4*)(W + (size_t)(n0 + ol) * D_ + k0 + dl);
            Bs[dl + 0][ol] = v.x; Bs[dl + 1][ol] = v.y;
            Bs[dl + 2][ol] = v.z; Bs[dl + 3][ol] = v.w;
        }
        __syncthreads();
#pragma unroll
        for (int k = 0; k < BKk; k++) {
            float4 a4 = *(const float4*)&As[k][ty * 4];
            float4 b4 = *(const float4*)&Bs[k][tx * 4];
            float av[4] = {a4.x, a4.y, a4.z, a4.w};
            float bw[4] = {b4.x, b4.y, b4.z, b4.w};
#pragma unroll
            for (int i = 0; i < 4; i++)
#pragma unroll
                for (int j = 0; j < 4; j++)
                    acc[i][j] += av[i] * bw[j];
        }
        __syncthreads();
    }

    if (!isV) {
#pragma unroll
        for (int i = 0; i < 4; i++) {
            size_t base = (size_t)(m0 + ty * 4 + i) * D_ + n0 + tx * 4;
            __nv_bfloat16 h[4], l[4];
#pragma unroll
            for (int j = 0; j < 4; j++)
                split_bf16(elu_f(acc[i][j] + bias[n0 + tx * 4 + j]), h[j], l[j]);
            *(__nv_bfloat162*)(g_Kh + base)     = __nv_bfloat162(h[0], h[1]);
            *(__nv_bfloat162*)(g_Kh + base + 2) = __nv_bfloat162(h[2], h[3]);
            *(__nv_bfloat162*)(g_Kl + base)     = __nv_bfloat162(l[0], l[1]);
            *(__nv_bfloat162*)(g_Kl + base + 2) = __nv_bfloat162(l[2], l[3]);
        }
    } else {
        const int sbase = s0 + ty * 4;
#pragma unroll
        for (int j = 0; j < 4; j++) {
            int o = n0 + tx * 4 + j;
            float bj = bias[o];
            size_t base = ((size_t)b * D_ + o) * S_ + sbase;
            __nv_bfloat16 h[4], l[4];
#pragma unroll
            for (int i = 0; i < 4; i++)
                split_bf16(elu_f(acc[i][j] + bj), h[i], l[i]);
            *(__nv_bfloat162*)(g_VTh + base)     = __nv_bfloat162(h[0], h[1]);
            *(__nv_bfloat162*)(g_VTh + base + 2) = __nv_bfloat162(h[2], h[3]);
            *(__nv_bfloat162*)(g_VTl + base)     = __nv_bfloat162(l[0], l[1]);
            *(__nv_bfloat162*)(g_VTl + base + 2) = __nv_bfloat162(l[2], l[3]);
        }
    }
}

// ===========================================================================
// In-place row softmax over S=2048; also emits bf16x2 split of the result.
// ===========================================================================
__global__ __launch_bounds__(256) void softmax_kernel(float* __restrict__ A)
{
    const size_t row = blockIdx.x;
    float* p = A + row * (size_t)S_;
    __nv_bfloat16* ph = g_Ah + row * (size_t)S_;
    __nv_bfloat16* pl = g_Al + row * (size_t)S_;
    const int t = threadIdx.x;

    float v[8];
    float m = -1e30f;
#pragma unroll
    for (int i = 0; i < 8; i++) { v[i] = p[i * 256 + t]; m = fmaxf(m, v[i]); }

    __shared__ float red[256];
    red[t] = m;
    __syncthreads();
    for (int s = 128; s > 0; s >>= 1) {
        if (t < s) red[t] = fmaxf(red[t], red[t + s]);
        __syncthreads();
    }
    m = red[0];
    __syncthreads();

    float sum = 0.f;
#pragma unroll
    for (int i = 0; i < 8; i++) { v[i] = __expf(v[i] - m); sum += v[i]; }
    red[t] = sum;
    __syncthreads();
    for (int s = 128; s > 0; s >>= 1) {
        if (t < s) red[t] += red[t + s];
        __syncthreads();
    }
    float inv = 1.f / red[0];
#pragma unroll
    for (int i = 0; i < 8; i++) {
        float a = v[i] * inv;
        p[i * 256 + t] = a;
        __nv_bfloat16 h, l;
        split_bf16(a, h, l);
        ph[i * 256 + t] = h;
        pl[i * 256 + t] = l;
    }
}

// ===========================================================================
extern "C" void kernel_launch(void* const* d_in, const int* in_sizes, int n_in,
                              void* d_out, int out_size)
{
    const float* H  = (const float*)d_in[0];
    const float* Wk = (const float*)d_in[1];
    const float* bk = (const float*)d_in[2];
    const float* Wv = (const float*)d_in[3];
    const float* bv = (const float*)d_in[4];
    const float* Q  = (const float*)d_in[5];

    float* out  = (float*)d_out;
    float* Cout = out;                          // [B, L, D]
    float* Aout = out + (size_t)B_ * L_ * D_;   // [B, L, S]

    static __nv_bfloat16 *gKh, *gKl, *gVTh, *gVTl, *gQh, *gQl, *gAh, *gAl;
    static bool init = false;
    if (!init) {
        cudaGetSymbolAddress((void**)&gKh,  g_Kh);
        cudaGetSymbolAddress((void**)&gKl,  g_Kl);
        cudaGetSymbolAddress((void**)&gVTh, g_VTh);
        cudaGetSymbolAddress((void**)&gVTl, g_VTl);
        cudaGetSymbolAddress((void**)&gQh,  g_Qh);
        cudaGetSymbolAddress((void**)&gQl,  g_Ql);
        cudaGetSymbolAddress((void**)&gAh,  g_Ah);
        cudaGetSymbolAddress((void**)&gAl,  g_Al);
        cudaFuncSetAttribute(gemm_mma, cudaFuncAttributeMaxDynamicSharedMemorySize, GEMM_SMEM);
        init = true;
    }

    const int MT = (L_ + TM - 1) / TM;  // 70

    // 0) split Q
    split_q<<<dim3(L_), 256>>>(Q);      // L_ blocks x 512 elems = L_*D_

    // 1) K/V projection + split
    kv_kernel<<<dim3(D_ / BN, (B_ * S_) / BM, 2), 256>>>(H, Wk, bk, Wv, bv);

    // 2) E = Q K^T -> Aout (fp32 scores)
    gemm_mma<<<dim3(S_ / TN, MT, B_), 256, GEMM_SMEM>>>(
        gQh, gQl, D_, 0,
        gKh, gKl, D_, (size_t)S_ * D_,
        Aout, S_, (size_t)L_ * S_,
        D_ / TK, L_);

    // 3) softmax rows (+ bf16x2 split of A)
    softmax_kernel<<<dim3(B_ * L_), 256>>>(Aout);

    // 4) C = A V -> Cout
    gemm_mma<<<dim3(D_ / TN, MT, B_), 256, GEMM_SMEM>>>(
        gAh, gAl, S_, (size_t)L_ * S_,
        gVTh, gVTl, S_, (size_t)D_ * S_,
        Cout, D_, (size_t)L_ * D_,
        S_ / TK, L_);
}

// round 5
// speedup vs baseline: 2.9039x; 1.1527x over previous
#include <cuda_runtime.h>
#include <cuda_bf16.h>
#include <math.h>
#include <cstdint>

#define B_ 4
#define D_ 512
#define S_ 2048
#define L_ 8921

// bf16x2 split operands
__device__ __nv_bfloat16 g_Kh[B_ * S_ * D_];
__device__ __nv_bfloat16 g_Kl[B_ * S_ * D_];
__device__ __nv_bfloat16 g_VTh[B_ * D_ * S_];
__device__ __nv_bfloat16 g_VTl[B_ * D_ * S_];
__device__ __nv_bfloat16 g_Qh[L_ * D_];
__device__ __nv_bfloat16 g_Ql[L_ * D_];
__device__ __nv_bfloat16 g_Ah[(size_t)B_ * L_ * S_];
__device__ __nv_bfloat16 g_Al[(size_t)B_ * L_ * S_];

// ---------------------------------------------------------------------------
// helpers
// ---------------------------------------------------------------------------
__device__ __forceinline__ uint32_t smem_to_u32(const void* p) {
    uint32_t a;
    asm("{ .reg .u64 t; cvta.to.shared.u64 t, %1; cvt.u32.u64 %0, t; }" : "=r"(a) : "l"(p));
    return a;
}
__device__ __forceinline__ void cp_async16(uint32_t dst, const void* src) {
    asm volatile("cp.async.cg.shared.global [%0], [%1], 16;" :: "r"(dst), "l"(src));
}
#define CP_COMMIT() asm volatile("cp.async.commit_group;" ::: "memory")
#define CP_WAIT(n)  asm volatile("cp.async.wait_group %0;" :: "n"(n) : "memory")

__device__ __forceinline__ void mma_bf16(float* d, const uint32_t* a, const uint32_t* b) {
    asm volatile(
        "mma.sync.aligned.m16n8k16.row.col.f32.bf16.bf16.f32 "
        "{%0,%1,%2,%3}, {%4,%5,%6,%7}, {%8,%9}, {%0,%1,%2,%3};"
        : "+f"(d[0]), "+f"(d[1]), "+f"(d[2]), "+f"(d[3])
        : "r"(a[0]), "r"(a[1]), "r"(a[2]), "r"(a[3]), "r"(b[0]), "r"(b[1]));
}
__device__ __forceinline__ void ldmx4(uint32_t* r, uint32_t addr) {
    asm volatile("ldmatrix.sync.aligned.m8n8.x4.shared.b16 {%0,%1,%2,%3}, [%4];"
        : "=r"(r[0]), "=r"(r[1]), "=r"(r[2]), "=r"(r[3]) : "r"(addr));
}

__device__ __forceinline__ float elu_f(float x) { return x > 0.f ? x : expm1f(x); }

__device__ __forceinline__ void split_bf16(float x, __nv_bfloat16& hi, __nv_bfloat16& lo) {
    hi = __float2bfloat16(x);
    lo = __float2bfloat16(x - __bfloat162float(hi));
}

// ===========================================================================
// bf16x2 mma.sync GEMM:  C[m,n] = sum_k A[m,k]*B[n,k]  (operands split hi/lo)
// Block 128x128, TK=32 (bf16), 8 warps (warp tile 64x32), 2-stage pipe,
// 2 CTAs/SM. smem rows padded to 80B -> ldmatrix conflict-free.
// ===========================================================================
#define TM 128
#define TN 128
#define TK 32
#define ROWB 80                          // 32 bf16 = 64B + 16B pad
#define SUB  (128 * ROWB)                // 10240 per sub-tile
#define STAGE (4 * SUB)                  // Ah | Al | Bh | Bl = 40960
#define NSTG 2
#define GEMM_SMEM (NSTG * STAGE)         // 81920 -> 2 CTAs/SM

__global__ __launch_bounds__(256, 2) void gemm_mma(
    const __nv_bfloat16* __restrict__ Ah, const __nv_bfloat16* __restrict__ Al,
    int lda, size_t sA,
    const __nv_bfloat16* __restrict__ Bh, const __nv_bfloat16* __restrict__ Bl,
    int ldb, size_t sB,
    float* __restrict__ C, int ldc, size_t sC,
    int kblocks, int Mtotal)
{
    extern __shared__ char smem[];
    const uint32_t sm0 = smem_to_u32(smem);

    const int t    = threadIdx.x;
    const int wid  = t >> 5, lane = t & 31;
    const int gid  = lane >> 2, tig = lane & 3;
    const int b    = blockIdx.z;
    const int m0   = blockIdx.y * TM;
    const int n0   = blockIdx.x * TN;

    Ah += (size_t)b * sA;  Al += (size_t)b * sA;
    Bh += (size_t)b * sB;  Bl += (size_t)b * sB;
    C  += (size_t)b * sC;

    const int wm0 = (wid & 1) * 64;
    const int wn0 = (wid >> 1) * 32;

    float acc[4][4][4];
#pragma unroll
    for (int i = 0; i < 4; i++)
#pragma unroll
        for (int j = 0; j < 4; j++)
#pragma unroll
            for (int q = 0; q < 4; q++) acc[i][j][q] = 0.f;

    // ---- stage loader: 2048 x 16B chunks (4 sub-tiles x 128 rows x 4 chunks)
    auto issue_stage = [&](int kb, int stg) {
        const uint32_t sbase = sm0 + stg * STAGE;
        const int k0 = kb * TK;
#pragma unroll
        for (int it = 0; it < 8; it++) {
            int idx = t + it * 256;
            int sub = idx >> 9;            // 0:Ah 1:Al 2:Bh 3:Bl
            int r   = (idx >> 2) & 127;
            int c   = idx & 3;
            uint32_t dst = sbase + sub * SUB + r * ROWB + c * 16;
            const __nv_bfloat16* src;
            if (sub < 2) {
                int gr = m0 + r; if (gr >= Mtotal) gr = Mtotal - 1;
                src = (sub == 0 ? Ah : Al) + (size_t)gr * lda + k0 + c * 8;
            } else {
                src = (sub == 2 ? Bh : Bl) + (size_t)(n0 + r) * ldb + k0 + c * 8;
            }
            cp_async16(dst, src);
        }
    };

    // ldmatrix lane addressing
    const int arow = lane & 15;                         // A rows 0..15
    const int aoff = (lane >> 4) * 16;                  // +16B for k 8..15
    const int bprow = ((lane >> 4) & 1) * 8 + (lane & 7); // B pair: rows 0..15
    const int bpoff = ((lane >> 3) & 1) * 16;             // +16B for k 8..15

    for (int p = 0; p < NSTG - 1 && p < kblocks; p++) { issue_stage(p, p); CP_COMMIT(); }

    for (int kb = 0; kb < kblocks; kb++) {
        CP_WAIT(NSTG - 2);
        __syncthreads();
        {
            int nk = kb + NSTG - 1;
            if (nk < kblocks) issue_stage(nk, nk % NSTG);
            CP_COMMIT();
        }

        const uint32_t sbase = sm0 + (kb % NSTG) * STAGE;

#pragma unroll
        for (int ks = 0; ks < 2; ks++) {               // 2 x k16 per TK=32
            uint32_t ah[4][4], al[4][4];
#pragma unroll
            for (int mt = 0; mt < 4; mt++) {
                uint32_t ra = (wm0 + mt * 16 + arow) * ROWB + ks * 32 + aoff;
                ldmx4(ah[mt], sbase + 0 * SUB + ra);
                ldmx4(al[mt], sbase + 1 * SUB + ra);
            }
#pragma unroll
            for (int p = 0; p < 2; p++) {              // nt pairs {0,1}, {2,3}
                uint32_t rb = (wn0 + p * 16 + bprow) * ROWB + ks * 32 + bpoff;
                uint32_t bh4[4], bl4[4];
                ldmx4(bh4, sbase + 2 * SUB + rb);      // bh[2p][0..1], bh[2p+1][0..1]
                ldmx4(bl4, sbase + 3 * SUB + rb);
#pragma unroll
                for (int h = 0; h < 2; h++) {
                    int nt = 2 * p + h;
#pragma unroll
                    for (int mt = 0; mt < 4; mt++) {
                        mma_bf16(acc[mt][nt], ah[mt], bh4 + 2 * h);
                        mma_bf16(acc[mt][nt], ah[mt], bl4 + 2 * h);
                        mma_bf16(acc[mt][nt], al[mt], bh4 + 2 * h);
                    }
                }
            }
        }
    }

    // ---- epilogue ----
#pragma unroll
    for (int mt = 0; mt < 4; mt++) {
        int r0 = m0 + wm0 + mt * 16 + gid;
#pragma unroll
        for (int nt = 0; nt < 4; nt++) {
            int c0 = n0 + wn0 + nt * 8 + 2 * tig;
            if (r0 < Mtotal)
                *(float2*)(C + (size_t)r0 * ldc + c0) =
                    make_float2(acc[mt][nt][0], acc[mt][nt][1]);
            if (r0 + 8 < Mtotal)
                *(float2*)(C + (size_t)(r0 + 8) * ldc + c0) =
                    make_float2(acc[mt][nt][2], acc[mt][nt][3]);
        }
    }
}

// ===========================================================================
// Q split:  g_Qh/g_Ql = bf16x2(Q).   L_ blocks x 512 elems
// ===========================================================================
__global__ __launch_bounds__(256) void split_q(const float* __restrict__ Q)
{
    int i = blockIdx.x * 512 + threadIdx.x * 2;
    float2 v = *(const float2*)(Q + i);
    __nv_bfloat16 h0, l0, h1, l1;
    split_bf16(v.x, h0, l0);
    split_bf16(v.y, h1, l1);
    *(__nv_bfloat162*)(g_Qh + i) = __nv_bfloat162(h0, h1);
    *(__nv_bfloat162*)(g_Ql + i) = __nv_bfloat162(l0, l1);
}

// ===========================================================================
// KV projection (fp32 SIMT), epilogue splits to bf16x2.
// ===========================================================================
#define BM 64
#define BN 64
#define BKk 16

__global__ __launch_bounds__(256) void kv_kernel(
    const float* __restrict__ H,
    const float* __restrict__ Wk, const float* __restrict__ bk,
    const float* __restrict__ Wv, const float* __restrict__ bv)
{
    const float* W    = blockIdx.z ? Wv : Wk;
    const float* bias = blockIdx.z ? bv : bk;
    const bool   isV  = blockIdx.z;

    __shared__ float As[BKk][BM];
    __shared__ float Bs[BKk][BN];

    const int m0 = blockIdx.y * BM;
    const int n0 = blockIdx.x * BN;
    const int b  = m0 / S_;
    const int s0 = m0 % S_;

    const int t  = threadIdx.x;
    const int tx = t & 15, ty = t >> 4;

    float acc[4][4] = {};
    const float* Hb = H + (size_t)b * D_ * S_;

    for (int k0 = 0; k0 < D_; k0 += BKk) {
        {
            int e = t * 4;
            int ml = e & 63, dl = e >> 6;
            float4 v = *(const float4*)(Hb + (size_t)(k0 + dl) * S_ + s0 + ml);
            *(float4*)&As[dl][ml] = v;
        }
        {
            int e = t * 4;
            int ol = e >> 4, dl = e & 15;
            float4 v = *(const float4*)(W + (size_t)(n0 + ol) * D_ + k0 + dl);
            Bs[dl + 0][ol] = v.x; Bs[dl + 1][ol] = v.y;
            Bs[dl + 2][ol] = v.z; Bs[dl + 3][ol] = v.w;
        }
        __syncthreads();
#pragma unroll
        for (int k = 0; k < BKk; k++) {
            float4 a4 = *(const float4*)&As[k][ty * 4];
            float4 b4 = *(const float4*)&Bs[k][tx * 4];
            float av[4] = {a4.x, a4.y, a4.z, a4.w};
            float bw[4] = {b4.x, b4.y, b4.z, b4.w};
#pragma unroll
            for (int i = 0; i < 4; i++)
#pragma unroll
                for (int j = 0; j < 4; j++)
                    acc[i][j] += av[i] * bw[j];
        }
        __syncthreads();
    }

    if (!isV) {
#pragma unroll
        for (int i = 0; i < 4; i++) {
            size_t base = (size_t)(m0 + ty * 4 + i) * D_ + n0 + tx * 4;
            __nv_bfloat16 h[4], l[4];
#pragma unroll
            for (int j = 0; j < 4; j++)
                split_bf16(elu_f(acc[i][j] + bias[n0 + tx * 4 + j]), h[j], l[j]);
            *(__nv_bfloat162*)(g_Kh + base)     = __nv_bfloat162(h[0], h[1]);
            *(__nv_bfloat162*)(g_Kh + base + 2) = __nv_bfloat162(h[2], h[3]);
            *(__nv_bfloat162*)(g_Kl + base)     = __nv_bfloat162(l[0], l[1]);
            *(__nv_bfloat162*)(g_Kl + base + 2) = __nv_bfloat162(l[2], l[3]);
        }
    } else {
        const int sbase = s0 + ty * 4;
#pragma unroll
        for (int j = 0; j < 4; j++) {
            int o = n0 + tx * 4 + j;
            float bj = bias[o];
            size_t base = ((size_t)b * D_ + o) * S_ + sbase;
            __nv_bfloat16 h[4], l[4];
#pragma unroll
            for (int i = 0; i < 4; i++)
                split_bf16(elu_f(acc[i][j] + bj), h[i], l[i]);
            *(__nv_bfloat162*)(g_VTh + base)     = __nv_bfloat162(h[0], h[1]);
            *(__nv_bfloat162*)(g_VTh + base + 2) = __nv_bfloat162(h[2], h[3]);
            *(__nv_bfloat162*)(g_VTl + base)     = __nv_bfloat162(l[0], l[1]);
            *(__nv_bfloat162*)(g_VTl + base + 2) = __nv_bfloat162(l[2], l[3]);
        }
    }
}

// ===========================================================================
// In-place row softmax over S=2048 (+ bf16x2 split). shfl reductions, float4.
// ===========================================================================
__global__ __launch_bounds__(256) void softmax_kernel(float* __restrict__ A)
{
    const size_t row = blockIdx.x;
    float* p = A + row * (size_t)S_;
    __nv_bfloat16* ph = g_Ah + row * (size_t)S_;
    __nv_bfloat16* pl = g_Al + row * (size_t)S_;
    const int t = threadIdx.x;
    const int lane = t & 31, wid = t >> 5;

    float4 va = *(const float4*)(p + t * 4);
    float4 vb = *(const float4*)(p + 1024 + t * 4);

    float m = fmaxf(fmaxf(fmaxf(va.x, va.y), fmaxf(va.z, va.w)),
                    fmaxf(fmaxf(vb.x, vb.y), fmaxf(vb.z, vb.w)));
#pragma unroll
    for (int o = 16; o > 0; o >>= 1) m = fmaxf(m, __shfl_xor_sync(0xffffffffu, m, o));

    __shared__ float red[8];
    if (lane == 0) red[wid] = m;
    __syncthreads();
    {
        float r = red[lane & 7];
#pragma unroll
        for (int o = 4; o > 0; o >>= 1) r = fmaxf(r, __shfl_xor_sync(0xffffffffu, r, o));
        m = r;
    }

    va.x = __expf(va.x - m); va.y = __expf(va.y - m);
    va.z = __expf(va.z - m); va.w = __expf(va.w - m);
    vb.x = __expf(vb.x - m); vb.y = __expf(vb.y - m);
    vb.z = __expf(vb.z - m); vb.w = __expf(vb.w - m);

    float s = va.x + va.y + va.z + va.w + vb.x + vb.y + vb.z + vb.w;
#pragma unroll
    for (int o = 16; o > 0; o >>= 1) s += __shfl_xor_sync(0xffffffffu, s, o);
    __syncthreads();
    if (lane == 0) red[wid] = s;
    __syncthreads();
    {
        float r = red[lane & 7];
#pragma unroll
        for (int o = 4; o > 0; o >>= 1) r += __shfl_xor_sync(0xffffffffu, r, o);
        s = r;
    }
    float inv = 1.f / s;

    va.x *= inv; va.y *= inv; va.z *= inv; va.w *= inv;
    vb.x *= inv; vb.y *= inv; vb.z *= inv; vb.w *= inv;

    *(float4*)(p + t * 4) = va;
    *(float4*)(p + 1024 + t * 4) = vb;

    __nv_bfloat16 h[8], l[8];
    split_bf16(va.x, h[0], l[0]); split_bf16(va.y, h[1], l[1]);
    split_bf16(va.z, h[2], l[2]); split_bf16(va.w, h[3], l[3]);
    split_bf16(vb.x, h[4], l[4]); split_bf16(vb.y, h[5], l[5]);
    split_bf16(vb.z, h[6], l[6]); split_bf16(vb.w, h[7], l[7]);

    *(__nv_bfloat162*)(ph + t * 4)     = __nv_bfloat162(h[0], h[1]);
    *(__nv_bfloat162*)(ph + t * 4 + 2) = __nv_bfloat162(h[2], h[3]);
    *(__nv_bfloat162*)(ph + 1024 + t * 4)     = __nv_bfloat162(h[4], h[5]);
    *(__nv_bfloat162*)(ph + 1024 + t * 4 + 2) = __nv_bfloat162(h[6], h[7]);
    *(__nv_bfloat162*)(pl + t * 4)     = __nv_bfloat162(l[0], l[1]);
    *(__nv_bfloat162*)(pl + t * 4 + 2) = __nv_bfloat162(l[2], l[3]);
    *(__nv_bfloat162*)(pl + 1024 + t * 4)     = __nv_bfloat162(l[4], l[5]);
    *(__nv_bfloat162*)(pl + 1024 + t * 4 + 2) = __nv_bfloat162(l[6], l[7]);
}

// ===========================================================================
extern "C" void kernel_launch(void* const* d_in, const int* in_sizes, int n_in,
                              void* d_out, int out_size)
{
    const float* H  = (const float*)d_in[0];
    const float* Wk = (const float*)d_in[1];
    const float* bk = (const float*)d_in[2];
    const float* Wv = (const float*)d_in[3];
    const float* bv = (const float*)d_in[4];
    const float* Q  = (const float*)d_in[5];

    float* out  = (float*)d_out;
    float* Cout = out;                          // [B, L, D]
    float* Aout = out + (size_t)B_ * L_ * D_;   // [B, L, S]

    static __nv_bfloat16 *gKh, *gKl, *gVTh, *gVTl, *gQh, *gQl, *gAh, *gAl;
    static bool init = false;
    if (!init) {
        cudaGetSymbolAddress((void**)&gKh,  g_Kh);
        cudaGetSymbolAddress((void**)&gKl,  g_Kl);
        cudaGetSymbolAddress((void**)&gVTh, g_VTh);
        cudaGetSymbolAddress((void**)&gVTl, g_VTl);
        cudaGetSymbolAddress((void**)&gQh,  g_Qh);
        cudaGetSymbolAddress((void**)&gQl,  g_Ql);
        cudaGetSymbolAddress((void**)&gAh,  g_Ah);
        cudaGetSymbolAddress((void**)&gAl,  g_Al);
        cudaFuncSetAttribute(gemm_mma, cudaFuncAttributeMaxDynamicSharedMemorySize, GEMM_SMEM);
        init = true;
    }

    const int MT = (L_ + TM - 1) / TM;  // 70

    split_q<<<dim3(L_), 256>>>(Q);
    kv_kernel<<<dim3(D_ / BN, (B_ * S_) / BM, 2), 256>>>(H, Wk, bk, Wv, bv);

    gemm_mma<<<dim3(S_ / TN, MT, B_), 256, GEMM_SMEM>>>(
        gQh, gQl, D_, 0,
        gKh, gKl, D_, (size_t)S_ * D_,
        Aout, S_, (size_t)L_ * S_,
        D_ / TK, L_);

    softmax_kernel<<<dim3(B_ * L_), 256>>>(Aout);

    gemm_mma<<<dim3(D_ / TN, MT, B_), 256, GEMM_SMEM>>>(
        gAh, gAl, S_, (size_t)L_ * S_,
        gVTh, gVTl, S_, (size_t)D_ * S_,
        Cout, D_, (size_t)L_ * D_,
        S_ / TK, L_);
}

// round 6
// speedup vs baseline: 3.1984x; 1.1014x over previous
#include <cuda_runtime.h>
#include <cuda_bf16.h>
#include <math.h>
#include <cstdint>

#define B_ 4
#define D_ 512
#define S_ 2048
#define L_ 8921

// bf16x2 split operands
__device__ __nv_bfloat16 g_Kh[B_ * S_ * D_];
__device__ __nv_bfloat16 g_Kl[B_ * S_ * D_];
__device__ __nv_bfloat16 g_VTh[B_ * D_ * S_];
__device__ __nv_bfloat16 g_VTl[B_ * D_ * S_];
__device__ __nv_bfloat16 g_Qh[L_ * D_];
__device__ __nv_bfloat16 g_Ql[L_ * D_];
__device__ __nv_bfloat16 g_Ah[(size_t)B_ * L_ * S_];
__device__ __nv_bfloat16 g_Al[(size_t)B_ * L_ * S_];
__device__ __nv_bfloat16 g_Hth[B_ * S_ * D_];   // H^T [B,S,D] hi
__device__ __nv_bfloat16 g_Htl[B_ * S_ * D_];   // H^T [B,S,D] lo
__device__ __nv_bfloat16 g_Wh[2 * D_ * D_];     // Wk | Wv hi
__device__ __nv_bfloat16 g_Wl[2 * D_ * D_];     // Wk | Wv lo

// ---------------------------------------------------------------------------
// helpers
// ---------------------------------------------------------------------------
__device__ __forceinline__ uint32_t smem_to_u32(const void* p) {
    uint32_t a;
    asm("{ .reg .u64 t; cvta.to.shared.u64 t, %1; cvt.u32.u64 %0, t; }" : "=r"(a) : "l"(p));
    return a;
}
__device__ __forceinline__ void cp_async16(uint32_t dst, const void* src) {
    asm volatile("cp.async.cg.shared.global [%0], [%1], 16;" :: "r"(dst), "l"(src));
}
#define CP_COMMIT() asm volatile("cp.async.commit_group;" ::: "memory")
#define CP_WAIT(n)  asm volatile("cp.async.wait_group %0;" :: "n"(n) : "memory")

__device__ __forceinline__ void mma_bf16(float* d, const uint32_t* a, const uint32_t* b) {
    asm volatile(
        "mma.sync.aligned.m16n8k16.row.col.f32.bf16.bf16.f32 "
        "{%0,%1,%2,%3}, {%4,%5,%6,%7}, {%8,%9}, {%0,%1,%2,%3};"
        : "+f"(d[0]), "+f"(d[1]), "+f"(d[2]), "+f"(d[3])
        : "r"(a[0]), "r"(a[1]), "r"(a[2]), "r"(a[3]), "r"(b[0]), "r"(b[1]));
}
__device__ __forceinline__ void ldmx4(uint32_t* r, uint32_t addr) {
    asm volatile("ldmatrix.sync.aligned.m8n8.x4.shared.b16 {%0,%1,%2,%3}, [%4];"
        : "=r"(r[0]), "=r"(r[1]), "=r"(r[2]), "=r"(r[3]) : "r"(addr));
}

__device__ __forceinline__ float elu_f(float x) { return x > 0.f ? x : expm1f(x); }

__device__ __forceinline__ void split_bf16(float x, __nv_bfloat16& hi, __nv_bfloat16& lo) {
    hi = __float2bfloat16(x);
    lo = __float2bfloat16(x - __bfloat162float(hi));
}

// ===========================================================================
// Shared GEMM tile config (bf16x3 split mma.sync)
// Block 128x128, TK=32, 8 warps (warp tile 64x32), 2-stage pipe, 2 CTAs/SM.
// ===========================================================================
#define TM 128
#define TN 128
#define TK 32
#define ROWB 80                          // 32 bf16 = 64B + 16B pad
#define SUB  (128 * ROWB)                // 10240 per sub-tile
#define STAGE (4 * SUB)                  // Ah | Al | Bh | Bl = 40960
#define NSTG 2
#define GEMM_SMEM (NSTG * STAGE)         // 81920 -> 2 CTAs/SM

// Mainloop macro-free core shared via a device function would cost regs;
// duplicate code in both kernels instead (identical structure).

// ---------------------------------------------------------------------------
// Main GEMM: C[m,n] = sum_k A[m,k]*B[n,k], fp32 output
// ---------------------------------------------------------------------------
__global__ __launch_bounds__(256, 2) void gemm_mma(
    const __nv_bfloat16* __restrict__ Ah, const __nv_bfloat16* __restrict__ Al,
    int lda, size_t sA,
    const __nv_bfloat16* __restrict__ Bh, const __nv_bfloat16* __restrict__ Bl,
    int ldb, size_t sB,
    float* __restrict__ C, int ldc, size_t sC,
    int kblocks, int Mtotal)
{
    extern __shared__ char smem[];
    const uint32_t sm0 = smem_to_u32(smem);

    const int t    = threadIdx.x;
    const int wid  = t >> 5, lane = t & 31;
    const int gid  = lane >> 2, tig = lane & 3;
    const int b    = blockIdx.z;
    const int m0   = blockIdx.y * TM;
    const int n0   = blockIdx.x * TN;

    Ah += (size_t)b * sA;  Al += (size_t)b * sA;
    Bh += (size_t)b * sB;  Bl += (size_t)b * sB;
    C  += (size_t)b * sC;

    const int wm0 = (wid & 1) * 64;
    const int wn0 = (wid >> 1) * 32;

    float acc[4][4][4];
#pragma unroll
    for (int i = 0; i < 4; i++)
#pragma unroll
        for (int j = 0; j < 4; j++)
#pragma unroll
            for (int q = 0; q < 4; q++) acc[i][j][q] = 0.f;

    auto issue_stage = [&](int kb, int stg) {
        const uint32_t sbase = sm0 + stg * STAGE;
        const int k0 = kb * TK;
#pragma unroll
        for (int it = 0; it < 8; it++) {
            int idx = t + it * 256;
            int sub = idx >> 9;
            int r   = (idx >> 2) & 127;
            int c   = idx & 3;
            uint32_t dst = sbase + sub * SUB + r * ROWB + c * 16;
            const __nv_bfloat16* src;
            if (sub < 2) {
                int gr = m0 + r; if (gr >= Mtotal) gr = Mtotal - 1;
                src = (sub == 0 ? Ah : Al) + (size_t)gr * lda + k0 + c * 8;
            } else {
                src = (sub == 2 ? Bh : Bl) + (size_t)(n0 + r) * ldb + k0 + c * 8;
            }
            cp_async16(dst, src);
        }
    };

    const int arow = lane & 15;
    const int aoff = (lane >> 4) * 16;
    const int bprow = ((lane >> 4) & 1) * 8 + (lane & 7);
    const int bpoff = ((lane >> 3) & 1) * 16;

    for (int p = 0; p < NSTG - 1 && p < kblocks; p++) { issue_stage(p, p); CP_COMMIT(); }

    for (int kb = 0; kb < kblocks; kb++) {
        CP_WAIT(NSTG - 2);
        __syncthreads();
        {
            int nk = kb + NSTG - 1;
            if (nk < kblocks) issue_stage(nk, nk % NSTG);
            CP_COMMIT();
        }

        const uint32_t sbase = sm0 + (kb % NSTG) * STAGE;

#pragma unroll
        for (int ks = 0; ks < 2; ks++) {
            uint32_t ah[4][4], al[4][4];
#pragma unroll
            for (int mt = 0; mt < 4; mt++) {
                uint32_t ra = (wm0 + mt * 16 + arow) * ROWB + ks * 32 + aoff;
                ldmx4(ah[mt], sbase + 0 * SUB + ra);
                ldmx4(al[mt], sbase + 1 * SUB + ra);
            }
#pragma unroll
            for (int p = 0; p < 2; p++) {
                uint32_t rb = (wn0 + p * 16 + bprow) * ROWB + ks * 32 + bpoff;
                uint32_t bh4[4], bl4[4];
                ldmx4(bh4, sbase + 2 * SUB + rb);
                ldmx4(bl4, sbase + 3 * SUB + rb);
#pragma unroll
                for (int h = 0; h < 2; h++) {
                    int nt = 2 * p + h;
#pragma unroll
                    for (int mt = 0; mt < 4; mt++) {
                        mma_bf16(acc[mt][nt], ah[mt], bh4 + 2 * h);
                        mma_bf16(acc[mt][nt], ah[mt], bl4 + 2 * h);
                        mma_bf16(acc[mt][nt], al[mt], bh4 + 2 * h);
                    }
                }
            }
        }
    }

#pragma unroll
    for (int mt = 0; mt < 4; mt++) {
        int r0 = m0 + wm0 + mt * 16 + gid;
#pragma unroll
        for (int nt = 0; nt < 4; nt++) {
            int c0 = n0 + wn0 + nt * 8 + 2 * tig;
            if (r0 < Mtotal)
                *(float2*)(C + (size_t)r0 * ldc + c0) =
                    make_float2(acc[mt][nt][0], acc[mt][nt][1]);
            if (r0 + 8 < Mtotal)
                *(float2*)(C + (size_t)(r0 + 8) * ldc + c0) =
                    make_float2(acc[mt][nt][2], acc[mt][nt][3]);
        }
    }
}

// ---------------------------------------------------------------------------
// KV GEMM: same core; epilogue = +bias, ELU, bf16 split. biasRow: bias[m] vs bias[n].
// All dims exact multiples (M in {2048,512}, N in {512,2048}, K=512).
// ---------------------------------------------------------------------------
__global__ __launch_bounds__(256, 2) void kv_gemm(
    const __nv_bfloat16* __restrict__ Ah, const __nv_bfloat16* __restrict__ Al,
    int lda, size_t sA,
    const __nv_bfloat16* __restrict__ Bh, const __nv_bfloat16* __restrict__ Bl,
    int ldb, size_t sB,
    __nv_bfloat16* __restrict__ Oh, __nv_bfloat16* __restrict__ Ol,
    int ldc, size_t sC,
    const float* __restrict__ bias, int biasRow,
    int kblocks)
{
    extern __shared__ char smem[];
    const uint32_t sm0 = smem_to_u32(smem);

    const int t    = threadIdx.x;
    const int wid  = t >> 5, lane = t & 31;
    const int gid  = lane >> 2, tig = lane & 3;
    const int b    = blockIdx.z;
    const int m0   = blockIdx.y * TM;
    const int n0   = blockIdx.x * TN;

    Ah += (size_t)b * sA;  Al += (size_t)b * sA;
    Bh += (size_t)b * sB;  Bl += (size_t)b * sB;
    Oh += (size_t)b * sC;  Ol += (size_t)b * sC;

    const int wm0 = (wid & 1) * 64;
    const int wn0 = (wid >> 1) * 32;

    float acc[4][4][4];
#pragma unroll
    for (int i = 0; i < 4; i++)
#pragma unroll
        for (int j = 0; j < 4; j++)
#pragma unroll
            for (int q = 0; q < 4; q++) acc[i][j][q] = 0.f;

    auto issue_stage = [&](int kb, int stg) {
        const uint32_t sbase = sm0 + stg * STAGE;
        const int k0 = kb * TK;
#pragma unroll
        for (int it = 0; it < 8; it++) {
            int idx = t + it * 256;
            int sub = idx >> 9;
            int r   = (idx >> 2) & 127;
            int c   = idx & 3;
            uint32_t dst = sbase + sub * SUB + r * ROWB + c * 16;
            const __nv_bfloat16* src;
            if (sub < 2)
                src = (sub == 0 ? Ah : Al) + (size_t)(m0 + r) * lda + k0 + c * 8;
            else
                src = (sub == 2 ? Bh : Bl) + (size_t)(n0 + r) * ldb + k0 + c * 8;
            cp_async16(dst, src);
        }
    };

    const int arow = lane & 15;
    const int aoff = (lane >> 4) * 16;
    const int bprow = ((lane >> 4) & 1) * 8 + (lane & 7);
    const int bpoff = ((lane >> 3) & 1) * 16;

    for (int p = 0; p < NSTG - 1 && p < kblocks; p++) { issue_stage(p, p); CP_COMMIT(); }

    for (int kb = 0; kb < kblocks; kb++) {
        CP_WAIT(NSTG - 2);
        __syncthreads();
        {
            int nk = kb + NSTG - 1;
            if (nk < kblocks) issue_stage(nk, nk % NSTG);
            CP_COMMIT();
        }

        const uint32_t sbase = sm0 + (kb % NSTG) * STAGE;

#pragma unroll
        for (int ks = 0; ks < 2; ks++) {
            uint32_t ah[4][4], al[4][4];
#pragma unroll
            for (int mt = 0; mt < 4; mt++) {
                uint32_t ra = (wm0 + mt * 16 + arow) * ROWB + ks * 32 + aoff;
                ldmx4(ah[mt], sbase + 0 * SUB + ra);
                ldmx4(al[mt], sbase + 1 * SUB + ra);
            }
#pragma unroll
            for (int p = 0; p < 2; p++) {
                uint32_t rb = (wn0 + p * 16 + bprow) * ROWB + ks * 32 + bpoff;
                uint32_t bh4[4], bl4[4];
                ldmx4(bh4, sbase + 2 * SUB + rb);
                ldmx4(bl4, sbase + 3 * SUB + rb);
#pragma unroll
                for (int h = 0; h < 2; h++) {
                    int nt = 2 * p + h;
#pragma unroll
                    for (int mt = 0; mt < 4; mt++) {
                        mma_bf16(acc[mt][nt], ah[mt], bh4 + 2 * h);
                        mma_bf16(acc[mt][nt], ah[mt], bl4 + 2 * h);
                        mma_bf16(acc[mt][nt], al[mt], bh4 + 2 * h);
                    }
                }
            }
        }
    }

    // epilogue: bias + ELU + split -> bf16x2 stores
#pragma unroll
    for (int mt = 0; mt < 4; mt++) {
        int r0 = m0 + wm0 + mt * 16 + gid;
#pragma unroll
        for (int nt = 0; nt < 4; nt++) {
            int c0 = n0 + wn0 + nt * 8 + 2 * tig;
            float b0, b1, b0r, b1r;
            if (biasRow) {
                b0 = b1 = bias[r0];
                b0r = b1r = bias[r0 + 8];
            } else {
                b0 = b0r = bias[c0];
                b1 = b1r = bias[c0 + 1];
            }
            __nv_bfloat16 h0, l0, h1, l1;
            split_bf16(elu_f(acc[mt][nt][0] + b0), h0, l0);
            split_bf16(elu_f(acc[mt][nt][1] + b1), h1, l1);
            *(__nv_bfloat162*)(Oh + (size_t)r0 * ldc + c0) = __nv_bfloat162(h0, h1);
            *(__nv_bfloat162*)(Ol + (size_t)r0 * ldc + c0) = __nv_bfloat162(l0, l1);
            split_bf16(elu_f(acc[mt][nt][2] + b0r), h0, l0);
            split_bf16(elu_f(acc[mt][nt][3] + b1r), h1, l1);
            *(__nv_bfloat162*)(Oh + (size_t)(r0 + 8) * ldc + c0) = __nv_bfloat162(h0, h1);
            *(__nv_bfloat162*)(Ol + (size_t)(r0 + 8) * ldc + c0) = __nv_bfloat162(l0, l1);
        }
    }
}

// ===========================================================================
// H^T split: H[b,d,s] -> g_Hth/g_Htl [b,s,d] bf16.  Tile 64d x 32s.
// grid (S/32, D/64, B), block (32,8)
// ===========================================================================
__global__ __launch_bounds__(256) void ht_split(const float* __restrict__ H)
{
    __shared__ float tile[64][33];
    const int b = blockIdx.z, s0 = blockIdx.x * 32, d0 = blockIdx.y * 64;
    const int tx = threadIdx.x, ty = threadIdx.y;
    const float* Hb = H + ((size_t)b * D_ + d0) * S_ + s0;

#pragma unroll
    for (int i = 0; i < 8; i++)
        tile[ty * 8 + i][tx] = Hb[(size_t)(ty * 8 + i) * S_ + tx];
    __syncthreads();

    const int t  = ty * 32 + tx;
    const int dd = t & 63, sr = t >> 6;
    const size_t obase = ((size_t)b * S_ + s0) * D_ + d0;
#pragma unroll
    for (int i = 0; i < 8; i++) {
        int s = sr + i * 4;
        float v = tile[dd][s];
        __nv_bfloat16 h, l;
        split_bf16(v, h, l);
        g_Hth[obase + (size_t)s * D_ + dd] = h;
        g_Htl[obase + (size_t)s * D_ + dd] = l;
    }
}

// ===========================================================================
// W split: Wk then Wv into g_Wh/g_Wl.  grid(512), block(256), float4 each.
// ===========================================================================
__global__ __launch_bounds__(256) void w_split(
    const float* __restrict__ Wk, const float* __restrict__ Wv)
{
    int i = blockIdx.x * 1024 + threadIdx.x * 4;
    const float* src = (i < D_ * D_) ? (Wk + i) : (Wv + i - D_ * D_);
    float4 v = *(const float4*)src;
    __nv_bfloat16 h[4], l[4];
    split_bf16(v.x, h[0], l[0]); split_bf16(v.y, h[1], l[1]);
    split_bf16(v.z, h[2], l[2]); split_bf16(v.w, h[3], l[3]);
    *(__nv_bfloat162*)(g_Wh + i)     = __nv_bfloat162(h[0], h[1]);
    *(__nv_bfloat162*)(g_Wh + i + 2) = __nv_bfloat162(h[2], h[3]);
    *(__nv_bfloat162*)(g_Wl + i)     = __nv_bfloat162(l[0], l[1]);
    *(__nv_bfloat162*)(g_Wl + i + 2) = __nv_bfloat162(l[2], l[3]);
}

// ===========================================================================
// Q split
// ===========================================================================
__global__ __launch_bounds__(256) void split_q(const float* __restrict__ Q)
{
    int i = blockIdx.x * 512 + threadIdx.x * 2;
    float2 v = *(const float2*)(Q + i);
    __nv_bfloat16 h0, l0, h1, l1;
    split_bf16(v.x, h0, l0);
    split_bf16(v.y, h1, l1);
    *(__nv_bfloat162*)(g_Qh + i) = __nv_bfloat162(h0, h1);
    *(__nv_bfloat162*)(g_Ql + i) = __nv_bfloat162(l0, l1);
}

// ===========================================================================
// In-place row softmax over S=2048 (+ bf16x2 split)
// ===========================================================================
__global__ __launch_bounds__(256) void softmax_kernel(float* __restrict__ A)
{
    const size_t row = blockIdx.x;
    float* p = A + row * (size_t)S_;
    __nv_bfloat16* ph = g_Ah + row * (size_t)S_;
    __nv_bfloat16* pl = g_Al + row * (size_t)S_;
    const int t = threadIdx.x;
    const int lane = t & 31, wid = t >> 5;

    float4 va = *(const float4*)(p + t * 4);
    float4 vb = *(const float4*)(p + 1024 + t * 4);

    float m = fmaxf(fmaxf(fmaxf(va.x, va.y), fmaxf(va.z, va.w)),
                    fmaxf(fmaxf(vb.x, vb.y), fmaxf(vb.z, vb.w)));
#pragma unroll
    for (int o = 16; o > 0; o >>= 1) m = fmaxf(m, __shfl_xor_sync(0xffffffffu, m, o));

    __shared__ float red[8];
    if (lane == 0) red[wid] = m;
    __syncthreads();
    {
        float r = red[lane & 7];
#pragma unroll
        for (int o = 4; o > 0; o >>= 1) r = fmaxf(r, __shfl_xor_sync(0xffffffffu, r, o));
        m = r;
    }

    va.x = __expf(va.x - m); va.y = __expf(va.y - m);
    va.z = __expf(va.z - m); va.w = __expf(va.w - m);
    vb.x = __expf(vb.x - m); vb.y = __expf(vb.y - m);
    vb.z = __expf(vb.z - m); vb.w = __expf(vb.w - m);

    float s = va.x + va.y + va.z + va.w + vb.x + vb.y + vb.z + vb.w;
#pragma unroll
    for (int o = 16; o > 0; o >>= 1) s += __shfl_xor_sync(0xffffffffu, s, o);
    __syncthreads();
    if (lane == 0) red[wid] = s;
    __syncthreads();
    {
        float r = red[lane & 7];
#pragma unroll
        for (int o = 4; o > 0; o >>= 1) r += __shfl_xor_sync(0xffffffffu, r, o);
        s = r;
    }
    float inv = 1.f / s;

    va.x *= inv; va.y *= inv; va.z *= inv; va.w *= inv;
    vb.x *= inv; vb.y *= inv; vb.z *= inv; vb.w *= inv;

    *(float4*)(p + t * 4) = va;
    *(float4*)(p + 1024 + t * 4) = vb;

    __nv_bfloat16 h[8], l[8];
    split_bf16(va.x, h[0], l[0]); split_bf16(va.y, h[1], l[1]);
    split_bf16(va.z, h[2], l[2]); split_bf16(va.w, h[3], l[3]);
    split_bf16(vb.x, h[4], l[4]); split_bf16(vb.y, h[5], l[5]);
    split_bf16(vb.z, h[6], l[6]); split_bf16(vb.w, h[7], l[7]);

    *(__nv_bfloat162*)(ph + t * 4)     = __nv_bfloat162(h[0], h[1]);
    *(__nv_bfloat162*)(ph + t * 4 + 2) = __nv_bfloat162(h[2], h[3]);
    *(__nv_bfloat162*)(ph + 1024 + t * 4)     = __nv_bfloat162(h[4], h[5]);
    *(__nv_bfloat162*)(ph + 1024 + t * 4 + 2) = __nv_bfloat162(h[6], h[7]);
    *(__nv_bfloat162*)(pl + t * 4)     = __nv_bfloat162(l[0], l[1]);
    *(__nv_bfloat162*)(pl + t * 4 + 2) = __nv_bfloat162(l[2], l[3]);
    *(__nv_bfloat162*)(pl + 1024 + t * 4)     = __nv_bfloat162(l[4], l[5]);
    *(__nv_bfloat162*)(pl + 1024 + t * 4 + 2) = __nv_bfloat162(l[6], l[7]);
}

// ===========================================================================
extern "C" void kernel_launch(void* const* d_in, const int* in_sizes, int n_in,
                              void* d_out, int out_size)
{
    const float* H  = (const float*)d_in[0];
    const float* Wk = (const float*)d_in[1];
    const float* bk = (const float*)d_in[2];
    const float* Wv = (const float*)d_in[3];
    const float* bv = (const float*)d_in[4];
    const float* Q  = (const float*)d_in[5];

    float* out  = (float*)d_out;
    float* Cout = out;                          // [B, L, D]
    float* Aout = out + (size_t)B_ * L_ * D_;   // [B, L, S]

    static __nv_bfloat16 *gKh, *gKl, *gVTh, *gVTl, *gQh, *gQl, *gAh, *gAl;
    static __nv_bfloat16 *gHth, *gHtl, *gWh, *gWl;
    static bool init = false;
    if (!init) {
        cudaGetSymbolAddress((void**)&gKh,  g_Kh);
        cudaGetSymbolAddress((void**)&gKl,  g_Kl);
        cudaGetSymbolAddress((void**)&gVTh, g_VTh);
        cudaGetSymbolAddress((void**)&gVTl, g_VTl);
        cudaGetSymbolAddress((void**)&gQh,  g_Qh);
        cudaGetSymbolAddress((void**)&gQl,  g_Ql);
        cudaGetSymbolAddress((void**)&gAh,  g_Ah);
        cudaGetSymbolAddress((void**)&gAl,  g_Al);
        cudaGetSymbolAddress((void**)&gHth, g_Hth);
        cudaGetSymbolAddress((void**)&gHtl, g_Htl);
        cudaGetSymbolAddress((void**)&gWh,  g_Wh);
        cudaGetSymbolAddress((void**)&gWl,  g_Wl);
        cudaFuncSetAttribute(gemm_mma, cudaFuncAttributeMaxDynamicSharedMemorySize, GEMM_SMEM);
        cudaFuncSetAttribute(kv_gemm, cudaFuncAttributeMaxDynamicSharedMemorySize, GEMM_SMEM);
        init = true;
    }

    const int MT = (L_ + TM - 1) / TM;  // 70

    // 0) splits / transpose
    split_q<<<dim3(L_), 256>>>(Q);
    ht_split<<<dim3(S_ / 32, D_ / 64, B_), dim3(32, 8)>>>(H);
    w_split<<<dim3(2 * D_ * D_ / 1024), 256>>>(Wk, Wv);

    // 1a) K[b,s,o] = H^T * Wk  (A=H^T, B=Wk, bias by col, out [s, o-contig])
    kv_gemm<<<dim3(D_ / TN, S_ / TM, B_), 256, GEMM_SMEM>>>(
        gHth, gHtl, D_, (size_t)S_ * D_,
        gWh, gWl, D_, 0,
        gKh, gKl, D_, (size_t)S_ * D_,
        bk, 0, D_ / TK);

    // 1b) V^T[b,o,s] = Wv * H^T  (A=Wv, B=H^T, bias by row, out [o, s-contig])
    kv_gemm<<<dim3(S_ / TN, D_ / TM, B_), 256, GEMM_SMEM>>>(
        gWh + D_ * D_, gWl + D_ * D_, D_, 0,
        gHth, gHtl, D_, (size_t)S_ * D_,
        gVTh, gVTl, S_, (size_t)D_ * S_,
        bv, 1, D_ / TK);

    // 2) E = Q K^T -> Aout
    gemm_mma<<<dim3(S_ / TN, MT, B_), 256, GEMM_SMEM>>>(
        gQh, gQl, D_, 0,
        gKh, gKl, D_, (size_t)S_ * D_,
        Aout, S_, (size_t)L_ * S_,
        D_ / TK, L_);

    // 3) softmax rows (+ bf16x2 split of A)
    softmax_kernel<<<dim3(B_ * L_), 256>>>(Aout);

    // 4) C = A V -> Cout
    gemm_mma<<<dim3(D_ / TN, MT, B_), 256, GEMM_SMEM>>>(
        gAh, gAl, S_, (size_t)L_ * S_,
        gVTh, gVTl, S_, (size_t)D_ * S_,
        Cout, D_, (size_t)L_ * D_,
        S_ / TK, L_);
}